// round 15
// baseline (speedup 1.0000x reference)
#include <cuda_runtime.h>
#include <cuda_fp16.h>
#include <stdint.h>
#include <cstdint>
#include <math.h>

#define TTOK  16384
#define HID   768
#define NHEAD 12
#define HDIM  64
#define SEQL  2048
#define NSEQ  8

__device__ float  g_xn [TTOK * HID];
__device__ __half g_xh [TTOK * HID];
__device__ __half g_q  [TTOK * HID];
__device__ __half g_k  [TTOK * HID];
__device__ __half g_v  [TTOK * HID];
__device__ __half g_att[TTOK * HID];
__device__ __half g_Wh [4][HID * HID];
__device__ float2 g_rope[SEQL * 32];   // (cos, sin) per (pos, freq)

__device__ __forceinline__ void ldsm4(unsigned a, unsigned &r0, unsigned &r1,
                                      unsigned &r2, unsigned &r3) {
    asm volatile("ldmatrix.sync.aligned.m8n8.x4.shared.b16 {%0,%1,%2,%3}, [%4];"
        : "=r"(r0), "=r"(r1), "=r"(r2), "=r"(r3) : "r"(a));
}
__device__ __forceinline__ void ldsm4t(unsigned a, unsigned &r0, unsigned &r1,
                                       unsigned &r2, unsigned &r3) {
    asm volatile("ldmatrix.sync.aligned.m8n8.x4.trans.shared.b16 {%0,%1,%2,%3}, [%4];"
        : "=r"(r0), "=r"(r1), "=r"(r2), "=r"(r3) : "r"(a));
}
__device__ __forceinline__ void mma16816(float* c, const unsigned* a,
                                         unsigned b0, unsigned b1) {
    asm volatile(
        "mma.sync.aligned.m16n8k16.row.col.f32.f16.f16.f32 "
        "{%0,%1,%2,%3},{%4,%5,%6,%7},{%8,%9},{%0,%1,%2,%3};"
        : "+f"(c[0]), "+f"(c[1]), "+f"(c[2]), "+f"(c[3])
        : "r"(a[0]), "r"(a[1]), "r"(a[2]), "r"(a[3]), "r"(b0), "r"(b1));
}
__device__ __forceinline__ void cpa16(unsigned d, const void* s) {
    asm volatile("cp.async.cg.shared.global [%0], [%1], 16;" :: "r"(d), "l"(s));
}
#define CP_COMMIT  asm volatile("cp.async.commit_group;")
#define CP_WAIT0   asm volatile("cp.async.wait_group 0;")
#define CP_WAIT1   asm volatile("cp.async.wait_group 1;")

__device__ __forceinline__ unsigned f22h(float x, float y) {
    __half2 h = __floats2half2_rn(x, y);
    return *reinterpret_cast<unsigned*>(&h);
}
__device__ __forceinline__ float ex2(float x) {
    float r; asm("ex2.approx.f32 %0, %1;" : "=f"(r) : "f"(x)); return r;
}

// softmax scale folded with log2(e): scores come out in log2 domain
#define QSCALE 0.1803368801111843f   // 0.125 * log2(e)

// ---- rope table: accurate sincosf, once ----
__global__ __launch_bounds__(256) void ropetab_kernel()
{
    int idx = blockIdx.x * 256 + threadIdx.x;   // pos*32 + i
    int pos = idx >> 5, i = idx & 31;
    float invf  = powf(10000.0f, -((float)(2 * i) / (float)HDIM));
    float theta = (float)pos * invf;
    float sn, cs; sincosf(theta, &sn, &cs);
    g_rope[idx] = make_float2(cs, sn);
}

// ---- weight fp32->fp16, once ----
__global__ __launch_bounds__(256) void w2h_kernel(
    const float* __restrict__ a, const float* __restrict__ b,
    const float* __restrict__ c, const float* __restrict__ d)
{
    int i = blockIdx.x * 256 + threadIdx.x;
    g_Wh[0][i] = __float2half_rn(a[i]);
    g_Wh[1][i] = __float2half_rn(b[i]);
    g_Wh[2][i] = __float2half_rn(c[i]);
    g_Wh[3][i] = __float2half_rn(d[i]);
}

// ---- LayerNorm: fp32 out (residual) + fp16 out (GEMM A) ----
__global__ __launch_bounds__(256) void ln_kernel(
    const float* __restrict__ x, const float* __restrict__ w,
    const float* __restrict__ b, float* __restrict__ xn, __half* __restrict__ xh)
{
    int row = blockIdx.x, tid = threadIdx.x;
    const float* xr = x + (size_t)row * HID;
    float v0 = xr[tid], v1 = xr[tid + 256], v2 = xr[tid + 512];
    float s = v0 + v1 + v2, ss = v0 * v0 + v1 * v1 + v2 * v2;
    #pragma unroll
    for (int o = 16; o > 0; o >>= 1) {
        s  += __shfl_xor_sync(0xffffffffu, s,  o);
        ss += __shfl_xor_sync(0xffffffffu, ss, o);
    }
    __shared__ float sm[8], sm2[8];
    if ((tid & 31) == 0) { sm[tid >> 5] = s; sm2[tid >> 5] = ss; }
    __syncthreads();
    float ts = 0.f, tss = 0.f;
    #pragma unroll
    for (int i = 0; i < 8; i++) { ts += sm[i]; tss += sm2[i]; }
    float mean = ts * (1.0f / HID);
    float var  = tss * (1.0f / HID) - mean * mean;
    float inv  = rsqrtf(var + 1e-12f);
    float* xo = xn + (size_t)row * HID;
    __half* xo2 = xh + (size_t)row * HID;
    float o0 = (v0 - mean) * inv * w[tid      ] + b[tid      ];
    float o1 = (v1 - mean) * inv * w[tid + 256] + b[tid + 256];
    float o2 = (v2 - mean) * inv * w[tid + 512] + b[tid + 512];
    xo[tid] = o0; xo[tid + 256] = o1; xo[tid + 512] = o2;
    xo2[tid] = __float2half_rn(o0);
    xo2[tid + 256] = __float2half_rn(o1);
    xo2[tid + 512] = __float2half_rn(o2);
}

// ---- fp16 GEMM body: 128x128 tile, BK=32, 8 warps, 3-stage cp.async ----
#define AS_LD 40
#define BS_LD 136
#define GSTG  3

template<bool HALF_OUT>
__device__ __forceinline__ void gemm_body(
    const __half* __restrict__ A, const __half* __restrict__ B,
    const float* __restrict__ bias, const float* __restrict__ addsrc,
    __half* __restrict__ outH, float* __restrict__ outF)
{
    extern __shared__ __align__(16) __half gsm[];

    int bx = blockIdx.x, by = blockIdx.y;
    int tid = threadIdx.x, w = tid >> 5, lane = tid & 31;
    int g = lane >> 2, qd = lane & 3;
    int mBase = (w >> 2) * 64, nBase = (w & 3) * 32;
    int i8 = lane & 7, sel = lane >> 3;
    int rowOff = i8 + (sel & 1) * 8;
    int colOff = (sel & 2) ? 8 : 0;

    int aRow = tid >> 1, aSeg = (tid & 1) * 16;
    int bK = tid >> 3, bSeg = (tid & 7) * 16;
    const __half* aG = A + (size_t)(by * 128 + aRow) * HID + aSeg;
    const __half* bG = B + (size_t)bK * HID + bx * 128 + bSeg;

    unsigned sA = (unsigned)__cvta_generic_to_shared(gsm);
    unsigned sB = sA + GSTG * 128 * AS_LD * 2;
    const unsigned bufA = 128 * AS_LD * 2, bufB = 32 * BS_LD * 2;
    unsigned dA = sA + (aRow * AS_LD + aSeg) * 2;
    unsigned dB = sB + (bK * BS_LD + bSeg) * 2;

    float acc[4][4][4];
    #pragma unroll
    for (int mt = 0; mt < 4; mt++)
        #pragma unroll
        for (int nt = 0; nt < 4; nt++)
            #pragma unroll
            for (int i = 0; i < 4; i++) acc[mt][nt][i] = 0.f;

    // prologue: stages 0,1
    #pragma unroll
    for (int s = 0; s < 2; s++) {
        int k0 = s * 32;
        cpa16(dA + s * bufA, aG + k0);
        cpa16(dA + s * bufA + 16, aG + k0 + 8);
        cpa16(dB + s * bufB, bG + (size_t)k0 * HID);
        cpa16(dB + s * bufB + 16, bG + (size_t)k0 * HID + 8);
        CP_COMMIT;
    }

    const int NI = HID / 32;  // 24
    int stage = 0, pst = 2;
    for (int c = 0; c < NI; c++) {
        CP_WAIT1;
        __syncthreads();
        // prefetch chunk c+2 into stage (c-1)%3 — freed by the barrier above
        if (c + 2 < NI) {
            int k0 = (c + 2) * 32;
            cpa16(dA + pst * bufA, aG + k0);
            cpa16(dA + pst * bufA + 16, aG + k0 + 8);
            cpa16(dB + pst * bufB, bG + (size_t)k0 * HID);
            cpa16(dB + pst * bufB + 16, bG + (size_t)k0 * HID + 8);
        }
        CP_COMMIT;

        unsigned cA = sA + stage * bufA;
        unsigned cB = sB + stage * bufB;
        #pragma unroll
        for (int kc = 0; kc < 2; kc++) {
            unsigned af[4][4];
            #pragma unroll
            for (int mt = 0; mt < 4; mt++) {
                unsigned a = cA +
                    ((mBase + mt * 16 + rowOff) * AS_LD + kc * 16 + colOff) * 2;
                ldsm4(a, af[mt][0], af[mt][1], af[mt][2], af[mt][3]);
            }
            unsigned bf[4][2];
            #pragma unroll
            for (int np = 0; np < 2; np++) {
                unsigned a = cB +
                    ((kc * 16 + rowOff) * BS_LD + nBase + np * 16 + colOff) * 2;
                unsigned r0, r1, r2, r3;
                ldsm4t(a, r0, r1, r2, r3);
                bf[2 * np][0] = r0;     bf[2 * np][1] = r1;
                bf[2 * np + 1][0] = r2; bf[2 * np + 1][1] = r3;
            }
            #pragma unroll
            for (int mt = 0; mt < 4; mt++)
                #pragma unroll
                for (int nt = 0; nt < 4; nt++)
                    mma16816(acc[mt][nt], af[mt], bf[nt][0], bf[nt][1]);
        }
        stage = (stage + 1 == GSTG) ? 0 : stage + 1;
        pst   = (pst   + 1 == GSTG) ? 0 : pst + 1;
    }

    #pragma unroll
    for (int mt = 0; mt < 4; mt++)
        #pragma unroll
        for (int hh = 0; hh < 2; hh++) {
            size_t row = (size_t)by * 128 + mBase + mt * 16 + g + hh * 8;
            #pragma unroll
            for (int nt = 0; nt < 4; nt++) {
                int col = bx * 128 + nBase + nt * 8 + 2 * qd;
                float ox = acc[mt][nt][hh * 2 + 0] + bias[col];
                float oy = acc[mt][nt][hh * 2 + 1] + bias[col + 1];
                if (HALF_OUT) {
                    *reinterpret_cast<__half2*>(outH + row * HID + col) =
                        __floats2half2_rn(ox, oy);
                } else {
                    const float2 r = *(const float2*)(addsrc + row * HID + col);
                    *(float2*)(outF + row * HID + col) =
                        make_float2(ox + r.x, oy + r.y);
                }
            }
        }
}

// Fused Q/K/V projection: blockIdx.z selects weight/bias/output
__global__ __launch_bounds__(256) void qkv_kernel(
    const __half* __restrict__ xh,
    const float* __restrict__ bq, const float* __restrict__ bk,
    const float* __restrict__ bv)
{
    int z = blockIdx.z;
    const float* bias = (z == 0) ? bq : (z == 1) ? bk : bv;
    __half* out = (z == 0) ? g_q : (z == 1) ? g_k : g_v;
    gemm_body<true>(xh, g_Wh[z], bias, nullptr, out, nullptr);
}

__global__ __launch_bounds__(256) void ogemm_kernel(
    const float* __restrict__ bo, float* __restrict__ out)
{
    gemm_body<false>(g_att, g_Wh[3], bo, g_xn, nullptr, out);
}

// ---- RoPE in place (fp16) via table; q pre-scaled by QSCALE ----
__global__ __launch_bounds__(NHEAD * 32) void rope_kernel(
    __half* __restrict__ q, __half* __restrict__ k)
{
    int t = blockIdx.x;
    int h = threadIdx.x >> 5, i = threadIdx.x & 31;
    int pos = t & (SEQL - 1);
    float2 cssn = g_rope[pos * 32 + i];
    float cs = cssn.x, sn = cssn.y;
    size_t base = (size_t)t * HID + h * HDIM;
    float x1 = __half2float(q[base + i]), x2 = __half2float(q[base + 32 + i]);
    q[base + i]      = __float2half_rn((x1 * cs - x2 * sn) * QSCALE);
    q[base + 32 + i] = __float2half_rn((x2 * cs + x1 * sn) * QSCALE);
    x1 = __half2float(k[base + i]); x2 = __half2float(k[base + 32 + i]);
    k[base + i]      = __float2half_rn(x1 * cs - x2 * sn);
    k[base + 32 + i] = __float2half_rn(x2 * cs + x1 * sn);
}

// ---- Flash attention fp16: Bq=256, Bkv=64, 8 warps x 32 q-rows,
//      3-stage KV pipeline, 2x fragment reuse (4 MMA per ldmatrix) ----
#define AT_LD 72
#define ASTG  3
#define BQ    256

__global__ __launch_bounds__(256) void attn_kernel(
    const __half* __restrict__ Q, const __half* __restrict__ Kg,
    const __half* __restrict__ Vg, __half* __restrict__ O)
{
    extern __shared__ __align__(16) __half smh[];
    __half* Qs = smh;                       // BQ x AT_LD
    const int KVB = 2 * 64 * AT_LD;         // halves per (K+V) stage

    int qt = blockIdx.x, h = blockIdx.y, sq = blockIdx.z;
    int tid = threadIdx.x, w = tid >> 5, lane = tid & 31;
    int g = lane >> 2, qd = lane & 3;
    int rBase = w * 32;
    const size_t seqBase = (size_t)sq * SEQL;
    int i8 = lane & 7, sel = lane >> 3;
    int rowOff = i8 + (sel & 1) * 8;
    int colOff = (sel & 2) ? 8 : 0;

    unsigned sBase = (unsigned)__cvta_generic_to_shared(smh);
    unsigned sQ = sBase;
    unsigned sKV0 = sBase + BQ * AT_LD * 2;

    {   // load Q tile: one row per thread (64 halves = 8 uint4)
        const uint4* qg = (const uint4*)(Q + (seqBase + (size_t)qt * BQ + tid) * HID
                                           + h * HDIM);
        uint4* qs = (uint4*)(Qs + tid * AT_LD);
        #pragma unroll
        for (int u = 0; u < 8; u++) qs[u] = qg[u];
    }

    int krow = tid >> 2, kseg = (tid & 3) * 16;
    const __half* kgp = Kg + (seqBase + krow) * HID + h * HDIM + kseg;
    const __half* vgp = Vg + (seqBase + krow) * HID + h * HDIM + kseg;
    unsigned dK = sKV0 + (krow * AT_LD + kseg) * 2;
    unsigned dV = dK + 64 * AT_LD * 2;

    // prologue: KV tiles 0,1 into stages 0,1
    #pragma unroll
    for (int s = 0; s < 2; s++) {
        size_t off = (size_t)s * 64 * HID;
        cpa16(dK + s * KVB * 2, kgp + off);
        cpa16(dK + s * KVB * 2 + 16, kgp + off + 8);
        cpa16(dV + s * KVB * 2, vgp + off);
        cpa16(dV + s * KVB * 2 + 16, vgp + off + 8);
        CP_COMMIT;
    }
    __syncthreads();  // Qs visible

    // Q fragments: 2 m-tiles x 4 k-chunks
    unsigned qf[2][4][4];
    #pragma unroll
    for (int mt = 0; mt < 2; mt++)
        #pragma unroll
        for (int kc = 0; kc < 4; kc++) {
            unsigned a = sQ + ((rBase + mt * 16 + rowOff) * AT_LD + kc * 16 + colOff) * 2;
            ldsm4(a, qf[mt][kc][0], qf[mt][kc][1], qf[mt][kc][2], qf[mt][kc][3]);
        }

    float oAcc[2][8][4];
    float m[2][2], l[2][2];
    #pragma unroll
    for (int mt = 0; mt < 2; mt++) {
        m[mt][0] = -1e30f; m[mt][1] = -1e30f;
        l[mt][0] = 0.f;    l[mt][1] = 0.f;
        #pragma unroll
        for (int nt = 0; nt < 8; nt++)
            #pragma unroll
            for (int i = 0; i < 4; i++) oAcc[mt][nt][i] = 0.f;
    }

    const int NKT = SEQL / 64;  // 32
    int stage = 0, pst = 2;
    for (int kt = 0; kt < NKT; kt++) {
        CP_WAIT1;
        __syncthreads();
        // prefetch tile kt+2 into stage (kt-1)%3 — freed by the barrier above
        if (kt + 2 < NKT) {
            size_t off = (size_t)(kt + 2) * 64 * HID;
            unsigned dKn = dK + pst * KVB * 2;
            unsigned dVn = dV + pst * KVB * 2;
            cpa16(dKn, kgp + off); cpa16(dKn + 16, kgp + off + 8);
            cpa16(dVn, vgp + off); cpa16(dVn + 16, vgp + off + 8);
        }
        CP_COMMIT;

        unsigned sK = sKV0 + stage * KVB * 2;
        unsigned sV = sK + 64 * AT_LD * 2;

        // S = Q K^T : each K ldmatrix feeds both m-tiles (8 MMAs per ldsm4)
        float sAcc[2][8][4];
        #pragma unroll
        for (int nt = 0; nt < 8; nt++) {
            #pragma unroll
            for (int mt = 0; mt < 2; mt++)
                #pragma unroll
                for (int i = 0; i < 4; i++) sAcc[mt][nt][i] = 0.f;
            unsigned r0, r1, r2, r3;
            unsigned a0 = sK + ((nt * 8 + i8) * AT_LD + sel * 8) * 2;
            ldsm4(a0, r0, r1, r2, r3);
            mma16816(sAcc[0][nt], qf[0][0], r0, r1);
            mma16816(sAcc[0][nt], qf[0][1], r2, r3);
            mma16816(sAcc[1][nt], qf[1][0], r0, r1);
            mma16816(sAcc[1][nt], qf[1][1], r2, r3);
            unsigned a1 = sK + ((nt * 8 + i8) * AT_LD + 32 + sel * 8) * 2;
            ldsm4(a1, r0, r1, r2, r3);
            mma16816(sAcc[0][nt], qf[0][2], r0, r1);
            mma16816(sAcc[0][nt], qf[0][3], r2, r3);
            mma16816(sAcc[1][nt], qf[1][2], r0, r1);
            mma16816(sAcc[1][nt], qf[1][3], r2, r3);
        }

        // online softmax in exp2 domain, per m-tile
        #pragma unroll
        for (int mt = 0; mt < 2; mt++) {
            float rmax1 = -1e30f, rmax2 = -1e30f;
            #pragma unroll
            for (int nt = 0; nt < 8; nt++) {
                rmax1 = fmaxf(rmax1, fmaxf(sAcc[mt][nt][0], sAcc[mt][nt][1]));
                rmax2 = fmaxf(rmax2, fmaxf(sAcc[mt][nt][2], sAcc[mt][nt][3]));
            }
            rmax1 = fmaxf(rmax1, __shfl_xor_sync(0xffffffffu, rmax1, 1));
            rmax1 = fmaxf(rmax1, __shfl_xor_sync(0xffffffffu, rmax1, 2));
            rmax2 = fmaxf(rmax2, __shfl_xor_sync(0xffffffffu, rmax2, 1));
            rmax2 = fmaxf(rmax2, __shfl_xor_sync(0xffffffffu, rmax2, 2));
            float mn1 = fmaxf(m[mt][0], rmax1), mn2 = fmaxf(m[mt][1], rmax2);
            float alpha1 = ex2(m[mt][0] - mn1), alpha2 = ex2(m[mt][1] - mn2);
            m[mt][0] = mn1; m[mt][1] = mn2;
            float rs1 = 0.f, rs2 = 0.f;
            #pragma unroll
            for (int nt = 0; nt < 8; nt++) {
                sAcc[mt][nt][0] = ex2(sAcc[mt][nt][0] - mn1);
                sAcc[mt][nt][1] = ex2(sAcc[mt][nt][1] - mn1);
                sAcc[mt][nt][2] = ex2(sAcc[mt][nt][2] - mn2);
                sAcc[mt][nt][3] = ex2(sAcc[mt][nt][3] - mn2);
                rs1 += sAcc[mt][nt][0] + sAcc[mt][nt][1];
                rs2 += sAcc[mt][nt][2] + sAcc[mt][nt][3];
            }
            rs1 += __shfl_xor_sync(0xffffffffu, rs1, 1);
            rs1 += __shfl_xor_sync(0xffffffffu, rs1, 2);
            rs2 += __shfl_xor_sync(0xffffffffu, rs2, 1);
            rs2 += __shfl_xor_sync(0xffffffffu, rs2, 2);
            l[mt][0] = l[mt][0] * alpha1 + rs1;
            l[mt][1] = l[mt][1] * alpha2 + rs2;
            #pragma unroll
            for (int nt = 0; nt < 8; nt++) {
                oAcc[mt][nt][0] *= alpha1; oAcc[mt][nt][1] *= alpha1;
                oAcc[mt][nt][2] *= alpha2; oAcc[mt][nt][3] *= alpha2;
            }
        }

        // O += P V : each V ldmatrix feeds both m-tiles
        #pragma unroll
        for (int kc = 0; kc < 4; kc++) {
            unsigned pf0[4], pf1[4];
            pf0[0] = f22h(sAcc[0][2 * kc][0], sAcc[0][2 * kc][1]);
            pf0[1] = f22h(sAcc[0][2 * kc][2], sAcc[0][2 * kc][3]);
            pf0[2] = f22h(sAcc[0][2 * kc + 1][0], sAcc[0][2 * kc + 1][1]);
            pf0[3] = f22h(sAcc[0][2 * kc + 1][2], sAcc[0][2 * kc + 1][3]);
            pf1[0] = f22h(sAcc[1][2 * kc][0], sAcc[1][2 * kc][1]);
            pf1[1] = f22h(sAcc[1][2 * kc][2], sAcc[1][2 * kc][3]);
            pf1[2] = f22h(sAcc[1][2 * kc + 1][0], sAcc[1][2 * kc + 1][1]);
            pf1[3] = f22h(sAcc[1][2 * kc + 1][2], sAcc[1][2 * kc + 1][3]);
            #pragma unroll
            for (int np = 0; np < 4; np++) {
                unsigned r0, r1, r2, r3;
                unsigned a = sV + ((kc * 16 + rowOff) * AT_LD + np * 16 + colOff) * 2;
                ldsm4t(a, r0, r1, r2, r3);
                mma16816(oAcc[0][2 * np],     pf0, r0, r1);
                mma16816(oAcc[0][2 * np + 1], pf0, r2, r3);
                mma16816(oAcc[1][2 * np],     pf1, r0, r1);
                mma16816(oAcc[1][2 * np + 1], pf1, r2, r3);
            }
        }
        stage = (stage + 1 == ASTG) ? 0 : stage + 1;
        pst   = (pst   + 1 == ASTG) ? 0 : pst + 1;
    }

    #pragma unroll
    for (int mt = 0; mt < 2; mt++) {
        float inv1 = 1.0f / l[mt][0], inv2 = 1.0f / l[mt][1];
        size_t row1 = seqBase + (size_t)qt * BQ + rBase + mt * 16 + g;
        size_t row2 = row1 + 8;
        #pragma unroll
        for (int nt = 0; nt < 8; nt++) {
            int col = h * HDIM + nt * 8 + 2 * qd;
            *reinterpret_cast<__half2*>(O + row1 * HID + col) =
                __floats2half2_rn(oAcc[mt][nt][0] * inv1, oAcc[mt][nt][1] * inv1);
            *reinterpret_cast<__half2*>(O + row2 * HID + col) =
                __floats2half2_rn(oAcc[mt][nt][2] * inv2, oAcc[mt][nt][3] * inv2);
        }
    }
}

// ---------------------------------------------------------------------------
extern "C" void kernel_launch(void* const* d_in, const int* in_sizes, int n_in,
                              void* d_out, int out_size)
{
    (void)in_sizes; (void)n_in; (void)out_size;
    const float* hs = (const float*)d_in[0];
    const float* nw = (const float*)d_in[3];
    const float* nb = (const float*)d_in[4];
    const float* Wq = (const float*)d_in[5];
    const float* bq = (const float*)d_in[6];
    const float* Wk = (const float*)d_in[7];
    const float* bk = (const float*)d_in[8];
    const float* Wv = (const float*)d_in[9];
    const float* bv = (const float*)d_in[10];
    const float* Wo = (const float*)d_in[11];
    const float* bo = (const float*)d_in[12];
    float* out = (float*)d_out;

    float* xn; __half *xh, *q, *k, *v, *att;
    cudaGetSymbolAddress((void**)&xn,  g_xn);
    cudaGetSymbolAddress((void**)&xh,  g_xh);
    cudaGetSymbolAddress((void**)&q,   g_q);
    cudaGetSymbolAddress((void**)&k,   g_k);
    cudaGetSymbolAddress((void**)&v,   g_v);
    cudaGetSymbolAddress((void**)&att, g_att);

    const int GEMM_SMEM = (GSTG * 128 * AS_LD + GSTG * 32 * BS_LD) * (int)sizeof(__half);
    const int ATTN_SMEM = (BQ * AT_LD + ASTG * 2 * 64 * AT_LD) * (int)sizeof(__half);
    static int attr_done = 0;
    if (!attr_done) {
        cudaFuncSetAttribute(qkv_kernel,
                             cudaFuncAttributeMaxDynamicSharedMemorySize, GEMM_SMEM);
        cudaFuncSetAttribute(ogemm_kernel,
                             cudaFuncAttributeMaxDynamicSharedMemorySize, GEMM_SMEM);
        cudaFuncSetAttribute(attn_kernel,
                             cudaFuncAttributeMaxDynamicSharedMemorySize, ATTN_SMEM);
        attr_done = 1;
    }

    ropetab_kernel<<<SEQL * 32 / 256, 256>>>();
    w2h_kernel<<<HID * HID / 256, 256>>>(Wq, Wk, Wv, Wo);
    ln_kernel<<<TTOK, 256>>>(hs, nw, nb, xn, xh);

    dim3 qkvgrid(HID / 128, TTOK / 128, 3);
    qkv_kernel<<<qkvgrid, 256, GEMM_SMEM>>>(xh, bq, bk, bv);

    rope_kernel<<<TTOK, NHEAD * 32>>>(q, k);

    dim3 agrid(SEQL / BQ, NHEAD, NSEQ);
    attn_kernel<<<agrid, 256, ATTN_SMEM>>>(q, k, v, att);

    dim3 ogrid(HID / 128, TTOK / 128);
    ogemm_kernel<<<ogrid, 256, GEMM_SMEM>>>(bo, out);
}

// round 17
// speedup vs baseline: 1.0601x; 1.0601x over previous
#include <cuda_runtime.h>
#include <cuda_fp16.h>
#include <stdint.h>
#include <cstdint>
#include <math.h>

#define TTOK  16384
#define HID   768
#define NHEAD 12
#define HDIM  64
#define SEQL  2048
#define NSEQ  8

__device__ float  g_xn [TTOK * HID];
__device__ __half g_xh [TTOK * HID];
__device__ __half g_q  [TTOK * HID];
__device__ __half g_k  [TTOK * HID];
__device__ __half g_v  [TTOK * HID];
__device__ __half g_att[TTOK * HID];
__device__ __half g_Wh [4][HID * HID];
__device__ float2 g_rope[SEQL * 32];   // (cos, sin) per (pos, freq)

__device__ __forceinline__ void ldsm4(unsigned a, unsigned &r0, unsigned &r1,
                                      unsigned &r2, unsigned &r3) {
    asm volatile("ldmatrix.sync.aligned.m8n8.x4.shared.b16 {%0,%1,%2,%3}, [%4];"
        : "=r"(r0), "=r"(r1), "=r"(r2), "=r"(r3) : "r"(a));
}
__device__ __forceinline__ void ldsm4t(unsigned a, unsigned &r0, unsigned &r1,
                                       unsigned &r2, unsigned &r3) {
    asm volatile("ldmatrix.sync.aligned.m8n8.x4.trans.shared.b16 {%0,%1,%2,%3}, [%4];"
        : "=r"(r0), "=r"(r1), "=r"(r2), "=r"(r3) : "r"(a));
}
__device__ __forceinline__ void mma16816(float* c, const unsigned* a,
                                         unsigned b0, unsigned b1) {
    asm volatile(
        "mma.sync.aligned.m16n8k16.row.col.f32.f16.f16.f32 "
        "{%0,%1,%2,%3},{%4,%5,%6,%7},{%8,%9},{%0,%1,%2,%3};"
        : "+f"(c[0]), "+f"(c[1]), "+f"(c[2]), "+f"(c[3])
        : "r"(a[0]), "r"(a[1]), "r"(a[2]), "r"(a[3]), "r"(b0), "r"(b1));
}
__device__ __forceinline__ void cpa16(unsigned d, const void* s) {
    asm volatile("cp.async.ca.shared.global [%0], [%1], 16;" :: "r"(d), "l"(s));
}
#define CP_COMMIT  asm volatile("cp.async.commit_group;")
#define CP_WAIT0   asm volatile("cp.async.wait_group 0;")
#define CP_WAIT1   asm volatile("cp.async.wait_group 1;")

__device__ __forceinline__ unsigned f22h(float x, float y) {
    __half2 h = __floats2half2_rn(x, y);
    return *reinterpret_cast<unsigned*>(&h);
}
__device__ __forceinline__ float ex2(float x) {
    float r; asm("ex2.approx.f32 %0, %1;" : "=f"(r) : "f"(x)); return r;
}

// softmax scale folded with log2(e): scores come out in log2 domain
#define QSCALE 0.1803368801111843f   // 0.125 * log2(e)

// ---- rope table: accurate sincosf, once ----
__global__ __launch_bounds__(256) void ropetab_kernel()
{
    int idx = blockIdx.x * 256 + threadIdx.x;   // pos*32 + i
    int pos = idx >> 5, i = idx & 31;
    float invf  = powf(10000.0f, -((float)(2 * i) / (float)HDIM));
    float theta = (float)pos * invf;
    float sn, cs; sincosf(theta, &sn, &cs);
    g_rope[idx] = make_float2(cs, sn);
}

// ---- weight fp32->fp16, once ----
__global__ __launch_bounds__(256) void w2h_kernel(
    const float* __restrict__ a, const float* __restrict__ b,
    const float* __restrict__ c, const float* __restrict__ d)
{
    int i = blockIdx.x * 256 + threadIdx.x;
    g_Wh[0][i] = __float2half_rn(a[i]);
    g_Wh[1][i] = __float2half_rn(b[i]);
    g_Wh[2][i] = __float2half_rn(c[i]);
    g_Wh[3][i] = __float2half_rn(d[i]);
}

// ---- LayerNorm: fp32 out (residual) + fp16 out (GEMM A) ----
__global__ __launch_bounds__(256) void ln_kernel(
    const float* __restrict__ x, const float* __restrict__ w,
    const float* __restrict__ b, float* __restrict__ xn, __half* __restrict__ xh)
{
    int row = blockIdx.x, tid = threadIdx.x;
    const float* xr = x + (size_t)row * HID;
    float v0 = xr[tid], v1 = xr[tid + 256], v2 = xr[tid + 512];
    float s = v0 + v1 + v2, ss = v0 * v0 + v1 * v1 + v2 * v2;
    #pragma unroll
    for (int o = 16; o > 0; o >>= 1) {
        s  += __shfl_xor_sync(0xffffffffu, s,  o);
        ss += __shfl_xor_sync(0xffffffffu, ss, o);
    }
    __shared__ float sm[8], sm2[8];
    if ((tid & 31) == 0) { sm[tid >> 5] = s; sm2[tid >> 5] = ss; }
    __syncthreads();
    float ts = 0.f, tss = 0.f;
    #pragma unroll
    for (int i = 0; i < 8; i++) { ts += sm[i]; tss += sm2[i]; }
    float mean = ts * (1.0f / HID);
    float var  = tss * (1.0f / HID) - mean * mean;
    float inv  = rsqrtf(var + 1e-12f);
    float* xo = xn + (size_t)row * HID;
    __half* xo2 = xh + (size_t)row * HID;
    float o0 = (v0 - mean) * inv * w[tid      ] + b[tid      ];
    float o1 = (v1 - mean) * inv * w[tid + 256] + b[tid + 256];
    float o2 = (v2 - mean) * inv * w[tid + 512] + b[tid + 512];
    xo[tid] = o0; xo[tid + 256] = o1; xo[tid + 512] = o2;
    xo2[tid] = __float2half_rn(o0);
    xo2[tid + 256] = __float2half_rn(o1);
    xo2[tid + 512] = __float2half_rn(o2);
}

// ---- fp16 GEMM body: 128x128 tile, BK=32, 8 warps, 3-stage cp.async ----
#define AS_LD 40
#define BS_LD 136
#define GSTG  3

template<bool HALF_OUT>
__device__ __forceinline__ void gemm_body(
    const __half* __restrict__ A, const __half* __restrict__ B,
    const float* __restrict__ bias, const float* __restrict__ addsrc,
    __half* __restrict__ outH, float* __restrict__ outF)
{
    extern __shared__ __align__(16) __half gsm[];

    int bx = blockIdx.x, by = blockIdx.y;
    int tid = threadIdx.x, w = tid >> 5, lane = tid & 31;
    int g = lane >> 2, qd = lane & 3;
    int mBase = (w >> 2) * 64, nBase = (w & 3) * 32;
    int i8 = lane & 7, sel = lane >> 3;
    int rowOff = i8 + (sel & 1) * 8;
    int colOff = (sel & 2) ? 8 : 0;

    int aRow = tid >> 1, aSeg = (tid & 1) * 16;
    int bK = tid >> 3, bSeg = (tid & 7) * 16;
    const __half* aG = A + (size_t)(by * 128 + aRow) * HID + aSeg;
    const __half* bG = B + (size_t)bK * HID + bx * 128 + bSeg;

    unsigned sA = (unsigned)__cvta_generic_to_shared(gsm);
    unsigned sB = sA + GSTG * 128 * AS_LD * 2;
    const unsigned bufA = 128 * AS_LD * 2, bufB = 32 * BS_LD * 2;
    unsigned dA = sA + (aRow * AS_LD + aSeg) * 2;
    unsigned dB = sB + (bK * BS_LD + bSeg) * 2;

    float acc[4][4][4];
    #pragma unroll
    for (int mt = 0; mt < 4; mt++)
        #pragma unroll
        for (int nt = 0; nt < 4; nt++)
            #pragma unroll
            for (int i = 0; i < 4; i++) acc[mt][nt][i] = 0.f;

    // prologue: stages 0,1
    #pragma unroll
    for (int s = 0; s < 2; s++) {
        int k0 = s * 32;
        cpa16(dA + s * bufA, aG + k0);
        cpa16(dA + s * bufA + 16, aG + k0 + 8);
        cpa16(dB + s * bufB, bG + (size_t)k0 * HID);
        cpa16(dB + s * bufB + 16, bG + (size_t)k0 * HID + 8);
        CP_COMMIT;
    }

    const int NI = HID / 32;  // 24
    int stage = 0, pst = 2;
    for (int c = 0; c < NI; c++) {
        CP_WAIT1;
        __syncthreads();
        // prefetch chunk c+2 into stage (c-1)%3 — freed by the barrier above
        if (c + 2 < NI) {
            int k0 = (c + 2) * 32;
            cpa16(dA + pst * bufA, aG + k0);
            cpa16(dA + pst * bufA + 16, aG + k0 + 8);
            cpa16(dB + pst * bufB, bG + (size_t)k0 * HID);
            cpa16(dB + pst * bufB + 16, bG + (size_t)k0 * HID + 8);
        }
        CP_COMMIT;

        unsigned cA = sA + stage * bufA;
        unsigned cB = sB + stage * bufB;
        #pragma unroll
        for (int kc = 0; kc < 2; kc++) {
            unsigned af[4][4];
            #pragma unroll
            for (int mt = 0; mt < 4; mt++) {
                unsigned a = cA +
                    ((mBase + mt * 16 + rowOff) * AS_LD + kc * 16 + colOff) * 2;
                ldsm4(a, af[mt][0], af[mt][1], af[mt][2], af[mt][3]);
            }
            unsigned bf[4][2];
            #pragma unroll
            for (int np = 0; np < 2; np++) {
                unsigned a = cB +
                    ((kc * 16 + rowOff) * BS_LD + nBase + np * 16 + colOff) * 2;
                unsigned r0, r1, r2, r3;
                ldsm4t(a, r0, r1, r2, r3);
                bf[2 * np][0] = r0;     bf[2 * np][1] = r1;
                bf[2 * np + 1][0] = r2; bf[2 * np + 1][1] = r3;
            }
            #pragma unroll
            for (int mt = 0; mt < 4; mt++)
                #pragma unroll
                for (int nt = 0; nt < 4; nt++)
                    mma16816(acc[mt][nt], af[mt], bf[nt][0], bf[nt][1]);
        }
        stage = (stage + 1 == GSTG) ? 0 : stage + 1;
        pst   = (pst   + 1 == GSTG) ? 0 : pst + 1;
    }

    #pragma unroll
    for (int mt = 0; mt < 4; mt++)
        #pragma unroll
        for (int hh = 0; hh < 2; hh++) {
            size_t row = (size_t)by * 128 + mBase + mt * 16 + g + hh * 8;
            #pragma unroll
            for (int nt = 0; nt < 4; nt++) {
                int col = bx * 128 + nBase + nt * 8 + 2 * qd;
                float ox = acc[mt][nt][hh * 2 + 0] + bias[col];
                float oy = acc[mt][nt][hh * 2 + 1] + bias[col + 1];
                if (HALF_OUT) {
                    *reinterpret_cast<__half2*>(outH + row * HID + col) =
                        __floats2half2_rn(ox, oy);
                } else {
                    const float2 r = *(const float2*)(addsrc + row * HID + col);
                    *(float2*)(outF + row * HID + col) =
                        make_float2(ox + r.x, oy + r.y);
                }
            }
        }
}

// Fused Q/K/V projection: blockIdx.z selects weight/bias/output
__global__ __launch_bounds__(256) void qkv_kernel(
    const __half* __restrict__ xh,
    const float* __restrict__ bq, const float* __restrict__ bk,
    const float* __restrict__ bv)
{
    int z = blockIdx.z;
    const float* bias = (z == 0) ? bq : (z == 1) ? bk : bv;
    __half* out = (z == 0) ? g_q : (z == 1) ? g_k : g_v;
    gemm_body<true>(xh, g_Wh[z], bias, nullptr, out, nullptr);
}

__global__ __launch_bounds__(256) void ogemm_kernel(
    const float* __restrict__ bo, float* __restrict__ out)
{
    gemm_body<false>(g_att, g_Wh[3], bo, g_xn, nullptr, out);
}

// ---- RoPE in place (fp16) via table; q pre-scaled by QSCALE ----
__global__ __launch_bounds__(NHEAD * 32) void rope_kernel(
    __half* __restrict__ q, __half* __restrict__ k)
{
    int t = blockIdx.x;
    int h = threadIdx.x >> 5, i = threadIdx.x & 31;
    int pos = t & (SEQL - 1);
    float2 cssn = g_rope[pos * 32 + i];
    float cs = cssn.x, sn = cssn.y;
    size_t base = (size_t)t * HID + h * HDIM;
    float x1 = __half2float(q[base + i]), x2 = __half2float(q[base + 32 + i]);
    q[base + i]      = __float2half_rn((x1 * cs - x2 * sn) * QSCALE);
    q[base + 32 + i] = __float2half_rn((x2 * cs + x1 * sn) * QSCALE);
    x1 = __half2float(k[base + i]); x2 = __half2float(k[base + 32 + i]);
    k[base + i]      = __float2half_rn(x1 * cs - x2 * sn);
    k[base + 32 + i] = __float2half_rn(x2 * cs + x1 * sn);
}

// ---- Flash attention fp16: Bq=128, Bkv=64, 8 warps x 16 rows,
//      3-stage KV pipeline, P in registers (round-12 config) ----
#define AT_LD 72
#define ASTG  3

__global__ __launch_bounds__(256) void attn_kernel(
    const __half* __restrict__ Q, const __half* __restrict__ Kg,
    const __half* __restrict__ Vg, __half* __restrict__ O)
{
    extern __shared__ __align__(16) __half smh[];
    __half* Qs = smh;
    const int KVB = 2 * 64 * AT_LD;  // halves per (K+V) stage

    int qt = blockIdx.x, h = blockIdx.y, sq = blockIdx.z;
    int tid = threadIdx.x, w = tid >> 5, lane = tid & 31;
    int g = lane >> 2, qd = lane & 3;
    int rBase = w * 16;
    const size_t seqBase = (size_t)sq * SEQL;
    int i8 = lane & 7, sel = lane >> 3;
    int rowOff = i8 + (sel & 1) * 8;
    int colOff = (sel & 2) ? 8 : 0;

    unsigned sBase = (unsigned)__cvta_generic_to_shared(smh);
    unsigned sQ = sBase;
    unsigned sKV0 = sBase + 128 * AT_LD * 2;

    {   // load Q tile
        int qrow = tid >> 1, qseg = (tid & 1) * 32;
        const uint4* qg = (const uint4*)(Q + (seqBase + (size_t)qt * 128 + qrow) * HID
                                           + h * HDIM + qseg);
        uint4* qs = (uint4*)(Qs + qrow * AT_LD + qseg);
        #pragma unroll
        for (int u = 0; u < 4; u++) qs[u] = qg[u];
    }

    int krow = tid >> 2, kseg = (tid & 3) * 16;
    const __half* kgp = Kg + (seqBase + krow) * HID + h * HDIM + kseg;
    const __half* vgp = Vg + (seqBase + krow) * HID + h * HDIM + kseg;
    unsigned dK = sKV0 + (krow * AT_LD + kseg) * 2;
    unsigned dV = dK + 64 * AT_LD * 2;

    // prologue: KV tiles 0,1 into stages 0,1
    #pragma unroll
    for (int s = 0; s < 2; s++) {
        size_t off = (size_t)s * 64 * HID;
        cpa16(dK + s * KVB * 2, kgp + off);
        cpa16(dK + s * KVB * 2 + 16, kgp + off + 8);
        cpa16(dV + s * KVB * 2, vgp + off);
        cpa16(dV + s * KVB * 2 + 16, vgp + off + 8);
        CP_COMMIT;
    }
    __syncthreads();  // Qs visible

    unsigned qf[4][4];
    #pragma unroll
    for (int kc = 0; kc < 4; kc++) {
        unsigned a = sQ + ((rBase + rowOff) * AT_LD + kc * 16 + colOff) * 2;
        ldsm4(a, qf[kc][0], qf[kc][1], qf[kc][2], qf[kc][3]);
    }

    float oAcc[8][4];
    #pragma unroll
    for (int nt = 0; nt < 8; nt++)
        #pragma unroll
        for (int i = 0; i < 4; i++) oAcc[nt][i] = 0.f;
    float m1 = -1e30f, m2 = -1e30f, l1 = 0.f, l2 = 0.f;

    const int NKT = SEQL / 64;  // 32
    int stage = 0, pst = 2;
    for (int kt = 0; kt < NKT; kt++) {
        CP_WAIT1;
        __syncthreads();
        // prefetch tile kt+2 into stage (kt-1)%3 — freed by the barrier above
        if (kt + 2 < NKT) {
            size_t off = (size_t)(kt + 2) * 64 * HID;
            unsigned dKn = dK + pst * KVB * 2;
            unsigned dVn = dV + pst * KVB * 2;
            cpa16(dKn, kgp + off); cpa16(dKn + 16, kgp + off + 8);
            cpa16(dVn, vgp + off); cpa16(dVn + 16, vgp + off + 8);
        }
        CP_COMMIT;

        unsigned sK = sKV0 + stage * KVB * 2;
        unsigned sV = sK + 64 * AT_LD * 2;

        // S = Q K^T (log2 domain: Q pre-scaled by 1/8*log2e)
        float sAcc[8][4];
        #pragma unroll
        for (int nt = 0; nt < 8; nt++) {
            #pragma unroll
            for (int i = 0; i < 4; i++) sAcc[nt][i] = 0.f;
            unsigned r0, r1, r2, r3;
            unsigned a0 = sK + ((nt * 8 + i8) * AT_LD + sel * 8) * 2;
            ldsm4(a0, r0, r1, r2, r3);
            mma16816(sAcc[nt], qf[0], r0, r1);
            mma16816(sAcc[nt], qf[1], r2, r3);
            unsigned a1 = sK + ((nt * 8 + i8) * AT_LD + 32 + sel * 8) * 2;
            ldsm4(a1, r0, r1, r2, r3);
            mma16816(sAcc[nt], qf[2], r0, r1);
            mma16816(sAcc[nt], qf[3], r2, r3);
        }

        // online softmax in exp2 domain (rows rBase+g, rBase+g+8)
        float rmax1 = -1e30f, rmax2 = -1e30f;
        #pragma unroll
        for (int nt = 0; nt < 8; nt++) {
            rmax1 = fmaxf(rmax1, fmaxf(sAcc[nt][0], sAcc[nt][1]));
            rmax2 = fmaxf(rmax2, fmaxf(sAcc[nt][2], sAcc[nt][3]));
        }
        rmax1 = fmaxf(rmax1, __shfl_xor_sync(0xffffffffu, rmax1, 1));
        rmax1 = fmaxf(rmax1, __shfl_xor_sync(0xffffffffu, rmax1, 2));
        rmax2 = fmaxf(rmax2, __shfl_xor_sync(0xffffffffu, rmax2, 1));
        rmax2 = fmaxf(rmax2, __shfl_xor_sync(0xffffffffu, rmax2, 2));
        float mn1 = fmaxf(m1, rmax1), mn2 = fmaxf(m2, rmax2);
        float alpha1 = ex2(m1 - mn1), alpha2 = ex2(m2 - mn2);
        m1 = mn1; m2 = mn2;
        float rs1 = 0.f, rs2 = 0.f;
        #pragma unroll
        for (int nt = 0; nt < 8; nt++) {
            sAcc[nt][0] = ex2(sAcc[nt][0] - m1);
            sAcc[nt][1] = ex2(sAcc[nt][1] - m1);
            sAcc[nt][2] = ex2(sAcc[nt][2] - m2);
            sAcc[nt][3] = ex2(sAcc[nt][3] - m2);
            rs1 += sAcc[nt][0] + sAcc[nt][1];
            rs2 += sAcc[nt][2] + sAcc[nt][3];
        }
        rs1 += __shfl_xor_sync(0xffffffffu, rs1, 1);
        rs1 += __shfl_xor_sync(0xffffffffu, rs1, 2);
        rs2 += __shfl_xor_sync(0xffffffffu, rs2, 1);
        rs2 += __shfl_xor_sync(0xffffffffu, rs2, 2);
        l1 = l1 * alpha1 + rs1;
        l2 = l2 * alpha2 + rs2;
        #pragma unroll
        for (int nt = 0; nt < 8; nt++) {
            oAcc[nt][0] *= alpha1; oAcc[nt][1] *= alpha1;
            oAcc[nt][2] *= alpha2; oAcc[nt][3] *= alpha2;
        }

        // O += P V (P packed in-register)
        #pragma unroll
        for (int kc = 0; kc < 4; kc++) {
            unsigned pf[4];
            pf[0] = f22h(sAcc[2 * kc][0], sAcc[2 * kc][1]);
            pf[1] = f22h(sAcc[2 * kc][2], sAcc[2 * kc][3]);
            pf[2] = f22h(sAcc[2 * kc + 1][0], sAcc[2 * kc + 1][1]);
            pf[3] = f22h(sAcc[2 * kc + 1][2], sAcc[2 * kc + 1][3]);
            #pragma unroll
            for (int np = 0; np < 4; np++) {
                unsigned r0, r1, r2, r3;
                unsigned a = sV + ((kc * 16 + rowOff) * AT_LD + np * 16 + colOff) * 2;
                ldsm4t(a, r0, r1, r2, r3);
                mma16816(oAcc[2 * np],     pf, r0, r1);
                mma16816(oAcc[2 * np + 1], pf, r2, r3);
            }
        }
        stage = (stage + 1 == ASTG) ? 0 : stage + 1;
        pst   = (pst   + 1 == ASTG) ? 0 : pst + 1;
    }

    float inv1 = 1.0f / l1, inv2 = 1.0f / l2;
    size_t row1 = seqBase + (size_t)qt * 128 + rBase + g;
    size_t row2 = row1 + 8;
    #pragma unroll
    for (int nt = 0; nt < 8; nt++) {
        int col = h * HDIM + nt * 8 + 2 * qd;
        *reinterpret_cast<__half2*>(O + row1 * HID + col) =
            __floats2half2_rn(oAcc[nt][0] * inv1, oAcc[nt][1] * inv1);
        *reinterpret_cast<__half2*>(O + row2 * HID + col) =
            __floats2half2_rn(oAcc[nt][2] * inv2, oAcc[nt][3] * inv2);
    }
}

// ---------------------------------------------------------------------------
extern "C" void kernel_launch(void* const* d_in, const int* in_sizes, int n_in,
                              void* d_out, int out_size)
{
    (void)in_sizes; (void)n_in; (void)out_size;
    const float* hs = (const float*)d_in[0];
    const float* nw = (const float*)d_in[3];
    const float* nb = (const float*)d_in[4];
    const float* Wq = (const float*)d_in[5];
    const float* bq = (const float*)d_in[6];
    const float* Wk = (const float*)d_in[7];
    const float* bk = (const float*)d_in[8];
    const float* Wv = (const float*)d_in[9];
    const float* bv = (const float*)d_in[10];
    const float* Wo = (const float*)d_in[11];
    const float* bo = (const float*)d_in[12];
    float* out = (float*)d_out;

    float* xn; __half *xh, *q, *k, *v, *att;
    cudaGetSymbolAddress((void**)&xn,  g_xn);
    cudaGetSymbolAddress((void**)&xh,  g_xh);
    cudaGetSymbolAddress((void**)&q,   g_q);
    cudaGetSymbolAddress((void**)&k,   g_k);
    cudaGetSymbolAddress((void**)&v,   g_v);
    cudaGetSymbolAddress((void**)&att, g_att);

    const int GEMM_SMEM = (GSTG * 128 * AS_LD + GSTG * 32 * BS_LD) * (int)sizeof(__half);
    const int ATTN_SMEM = (128 * AT_LD + ASTG * 2 * 64 * AT_LD) * (int)sizeof(__half);
    static int attr_done = 0;
    if (!attr_done) {
        cudaFuncSetAttribute(qkv_kernel,
                             cudaFuncAttributeMaxDynamicSharedMemorySize, GEMM_SMEM);
        cudaFuncSetAttribute(ogemm_kernel,
                             cudaFuncAttributeMaxDynamicSharedMemorySize, GEMM_SMEM);
        cudaFuncSetAttribute(attn_kernel,
                             cudaFuncAttributeMaxDynamicSharedMemorySize, ATTN_SMEM);
        attr_done = 1;
    }

    ropetab_kernel<<<SEQL * 32 / 256, 256>>>();
    w2h_kernel<<<HID * HID / 256, 256>>>(Wq, Wk, Wv, Wo);
    ln_kernel<<<TTOK, 256>>>(hs, nw, nb, xn, xh);

    dim3 qkvgrid(HID / 128, TTOK / 128, 3);
    qkv_kernel<<<qkvgrid, 256, GEMM_SMEM>>>(xh, bq, bk, bv);

    rope_kernel<<<TTOK, NHEAD * 32>>>(q, k);

    dim3 agrid(SEQL / 128, NHEAD, NSEQ);
    attn_kernel<<<agrid, 256, ATTN_SMEM>>>(q, k, v, att);

    dim3 ogrid(HID / 128, TTOK / 128);
    ogemm_kernel<<<ogrid, 256, GEMM_SMEM>>>(bo, out);
}